// round 1
// baseline (speedup 1.0000x reference)
#include <cuda_runtime.h>
#include <math.h>

#define B_ 16
#define N_ 16384
#define D_ 64
#define K_ 64
#define T_ 256            // points per tile
#define SPLIT_ 16         // CTAs per batch
#define TILES_ (N_ / SPLIT_ / T_)   // 4
#define STRIDE_ 68        // padded row stride (floats) for xs/qs
#define SLOT_ (K_ + 2 * K_ * D_)    // 8256 floats per partial slot
#define OUTB_ SLOT_

// Partial accumulators: one slot per (batch, split). Written fully each launch
// (no zeroing needed), summed deterministically in the finalize kernel.
__device__ __align__(16) float g_part[(size_t)B_ * SPLIT_ * SLOT_];

// Dynamic shared layout (float offsets)
#define SM_IVH 0                         // -0.5f / var      [K*D]
#define SM_AA  (K_ * D_)                 // mu / var         [K*D]
#define SM_CC  (2 * K_ * D_)             // per-k constant   [K]
#define SM_XS  (2 * K_ * D_ + K_)        // x tile           [T * STRIDE]
#define SM_QS  (SM_XS + T_ * STRIDE_)    // Q tile           [T * STRIDE]
#define SM_FLOATS (SM_QS + T_ * STRIDE_)

__global__ __launch_bounds__(256, 1) void fv_main(
    const float* __restrict__ x, const float* __restrict__ pi,
    const float* __restrict__ mu, const float* __restrict__ var)
{
    extern __shared__ float sm[];
    float* ivh = sm + SM_IVH;
    float* aa  = sm + SM_AA;
    float* cc  = sm + SM_CC;
    float* xs  = sm + SM_XS;
    float* qs  = sm + SM_QS;

    const int tid = threadIdx.x;
    const int b = blockIdx.y;
    const int s = blockIdx.x;

    // ---- stage per-component params in shared ----
    for (int i = tid; i < K_ * D_; i += 256) {
        float v = var[i];
        float iv = 1.0f / v;
        ivh[i] = -0.5f * iv;
        aa[i]  = mu[i] * iv;
    }
    if (tid < K_) {
        float acc = 0.0f;
        for (int d = 0; d < D_; ++d) {
            float v = var[tid * D_ + d];
            float m = mu[tid * D_ + d];
            acc += logf(v) + m * m / v;
        }
        // log pi - 0.5*(D*log(2pi) + logdet + mu^T Sigma^-1 mu)
        cc[tid] = logf(pi[tid]) - 0.5f * ((float)D_ * 1.83787706640934548356f + acc);
    }
    // (first tile's __syncthreads below publishes ivh/aa/cc)

    const int tk = tid >> 4;   // 0..15 -> 4 k-rows each
    const int td = tid & 15;   // 0..15 -> 4 d-cols each
    float accX[4][4]  = {};
    float accX2[4][4] = {};
    float qsum1 = 0.0f;

    const int n_base = s * (N_ / SPLIT_);

    for (int tile = 0; tile < TILES_; ++tile) {
        const int n0 = n_base + tile * T_;
        // ---- coalesced load of x tile into padded shared ----
        const float4* xg = (const float4*)(x + ((size_t)b * N_ + n0) * D_);
        for (int i = tid; i < T_ * D_ / 4; i += 256) {
            float4 v = xg[i];
            int row = i >> 4;         // 16 float4 per 64-wide row
            int c4  = i & 15;
            *(float4*)(xs + row * STRIDE_ + c4 * 4) = v;
        }
        __syncthreads();

        // ---- phase 1: per-point responsibilities (thread t = point t) ----
        {
            float lp[K_];
            #pragma unroll
            for (int k = 0; k < K_; ++k) lp[k] = cc[k];
            const float* xr = xs + tid * STRIDE_;
            for (int d4 = 0; d4 < D_; d4 += 4) {
                float4 xv = *(const float4*)(xr + d4);
                float x2a = xv.x * xv.x, x2b = xv.y * xv.y;
                float x2c = xv.z * xv.z, x2d = xv.w * xv.w;
                #pragma unroll
                for (int k = 0; k < K_; ++k) {
                    float4 ih = *(const float4*)(ivh + k * D_ + d4);
                    float4 av = *(const float4*)(aa  + k * D_ + d4);
                    float t = lp[k];
                    t = fmaf(x2a, ih.x, t); t = fmaf(xv.x, av.x, t);
                    t = fmaf(x2b, ih.y, t); t = fmaf(xv.y, av.y, t);
                    t = fmaf(x2c, ih.z, t); t = fmaf(xv.z, av.z, t);
                    t = fmaf(x2d, ih.w, t); t = fmaf(xv.w, av.w, t);
                    lp[k] = t;
                }
            }
            float mx = lp[0];
            #pragma unroll
            for (int k = 1; k < K_; ++k) mx = fmaxf(mx, lp[k]);
            float sum = 0.0f;
            #pragma unroll
            for (int k = 0; k < K_; ++k) {
                float e = __expf(lp[k] - mx);
                lp[k] = e;
                sum += e;
            }
            float inv = __fdividef(1.0f, sum);
            float* qr = qs + tid * STRIDE_;
            #pragma unroll
            for (int k = 0; k < K_; ++k) qr[k] = lp[k] * inv;
        }
        __syncthreads();

        // ---- phase 2: rank-T update of 64x64 Q_x and Q_x2 blocks ----
        for (int n = 0; n < T_; ++n) {
            float4 q  = *(const float4*)(qs + n * STRIDE_ + tk * 4);
            float4 xv = *(const float4*)(xs + n * STRIDE_ + td * 4);
            float qv[4]  = {q.x, q.y, q.z, q.w};
            float xvv[4] = {xv.x, xv.y, xv.z, xv.w};
            float x2v[4] = {xv.x * xv.x, xv.y * xv.y, xv.z * xv.z, xv.w * xv.w};
            #pragma unroll
            for (int i = 0; i < 4; ++i) {
                #pragma unroll
                for (int j = 0; j < 4; ++j) {
                    accX[i][j]  = fmaf(qv[i], xvv[j], accX[i][j]);
                    accX2[i][j] = fmaf(qv[i], x2v[j], accX2[i][j]);
                }
            }
        }
        // per-k Q sums (threads 0..63 own one k each; conflict-free column reads)
        if (tid < K_) {
            float a = 0.0f;
            for (int n = 0; n < T_; ++n) a += qs[n * STRIDE_ + tid];
            qsum1 += a;
        }
        __syncthreads();
    }

    // ---- flush partials (deterministic, per-CTA slot) ----
    float* slot = g_part + ((size_t)b * SPLIT_ + s) * SLOT_;
    if (tid < K_) slot[tid] = qsum1;
    float* qxs  = slot + K_;
    float* qx2s = slot + K_ + K_ * D_;
    #pragma unroll
    for (int i = 0; i < 4; ++i) {
        int k = tk * 4 + i;
        *(float4*)(qxs  + k * D_ + td * 4) =
            make_float4(accX[i][0], accX[i][1], accX[i][2], accX[i][3]);
        *(float4*)(qx2s + k * D_ + td * 4) =
            make_float4(accX2[i][0], accX2[i][1], accX2[i][2], accX2[i][3]);
    }
}

__global__ __launch_bounds__(256) void fv_final(
    const float* __restrict__ pi, const float* __restrict__ mu,
    const float* __restrict__ var, float* __restrict__ out)
{
    const int b = blockIdx.x;
    const int tid = threadIdx.x;
    __shared__ float qsum_s[K_];
    const float* base = g_part + (size_t)b * SPLIT_ * SLOT_;
    const float inv_n = 1.0f / (float)N_;

    if (tid < K_) {
        float ssum = 0.0f;
        for (int t = 0; t < SPLIT_; ++t) ssum += base[(size_t)t * SLOT_ + tid];
        ssum *= inv_n;
        qsum_s[tid] = ssum;
        out[(size_t)b * OUTB_ + tid] = ssum - pi[tid];   // d_pi
    }
    __syncthreads();

    for (int idx = tid; idx < K_ * D_; idx += blockDim.x) {
        float qx = 0.0f, qx2 = 0.0f;
        for (int t = 0; t < SPLIT_; ++t) {
            const float* sl = base + (size_t)t * SLOT_;
            qx  += sl[K_ + idx];
            qx2 += sl[K_ + K_ * D_ + idx];
        }
        qx *= inv_n; qx2 *= inv_n;
        int k = idx >> 6;
        float m = mu[idx];
        float v = var[idx];
        float qsv = qsum_s[k];
        out[(size_t)b * OUTB_ + K_ + idx] = qx - qsv * m;                       // d_mu
        out[(size_t)b * OUTB_ + K_ + K_ * D_ + idx] =
            -qx2 - qsv * m * m + qsv * v + 2.0f * qx * m;                       // d_sigma
    }
}

extern "C" void kernel_launch(void* const* d_in, const int* in_sizes, int n_in,
                              void* d_out, int out_size)
{
    const float* x   = (const float*)d_in[0];
    const float* pi  = (const float*)d_in[1];
    const float* mu  = (const float*)d_in[2];
    const float* var = (const float*)d_in[3];
    float* out = (float*)d_out;

    size_t smem = (size_t)SM_FLOATS * sizeof(float);  // 172,288 bytes
    cudaFuncSetAttribute(fv_main, cudaFuncAttributeMaxDynamicSharedMemorySize, (int)smem);

    dim3 grid(SPLIT_, B_);
    fv_main<<<grid, 256, smem>>>(x, pi, mu, var);
    fv_final<<<B_, 256>>>(pi, mu, var, out);
}

// round 6
// speedup vs baseline: 1.3328x; 1.3328x over previous
#include <cuda_runtime.h>
#include <math.h>

#define B_ 16
#define N_ 16384
#define D_ 64
#define K_ 64
#define T_ 128            // points per tile
#define SPLIT_ 16         // CTAs per batch
#define TILES_ (N_ / SPLIT_ / T_)   // 8
#define XST_ 68           // padded row stride (floats) for xs/qs
#define SLOT_ (K_ + 2 * K_ * D_)    // 8256 floats per partial slot

typedef unsigned long long u64;

// ---- packed f32x2 helpers (sm_100+ PTX) ----
__device__ __forceinline__ u64 pk2(float a, float b) {
    u64 r; asm("mov.b64 %0, {%1, %2};" : "=l"(r) : "f"(a), "f"(b)); return r;
}
__device__ __forceinline__ void up2(float& a, float& b, u64 v) {
    asm("mov.b64 {%0, %1}, %2;" : "=f"(a), "=f"(b) : "l"(v));
}
__device__ __forceinline__ u64 fma2(u64 a, u64 b, u64 c) {
    u64 r; asm("fma.rn.f32x2 %0, %1, %2, %3;" : "=l"(r) : "l"(a), "l"(b), "l"(c)); return r;
}
__device__ __forceinline__ u64 mul2(u64 a, u64 b) {
    u64 r; asm("mul.rn.f32x2 %0, %1, %2;" : "=l"(r) : "l"(a), "l"(b)); return r;
}
__device__ __forceinline__ u64 add2(u64 a, u64 b) {
    u64 r; asm("add.rn.f32x2 %0, %1, %2;" : "=l"(r) : "l"(a), "l"(b)); return r;
}

// Partial accumulators: one slot per (batch, split). Fully written each launch.
__device__ __align__(16) float g_part[(size_t)B_ * SPLIT_ * SLOT_];

// Dynamic shared layout (float offsets)
#define SM_IVT 0                          // -0.5/var, transposed [d][k]   K*D
#define SM_AAT (K_ * D_)                  // mu/var, transposed [d][k]     K*D
#define SM_CC  (2 * K_ * D_)              // per-k log const               K
#define SM_XS  (2 * K_ * D_ + K_)        // x tile  [T][XST]
#define SM_QS  (SM_XS + T_ * XST_)       // Q tile  [T][XST]
#define SM_FLOATS (SM_QS + T_ * XST_)    // 25664 floats = 102656 B

__global__ __launch_bounds__(256, 2) void fv_main(
    const float* __restrict__ x, const float* __restrict__ pi,
    const float* __restrict__ mu, const float* __restrict__ var)
{
    extern __shared__ float sm[];
    float* ivhT = sm + SM_IVT;
    float* aaT  = sm + SM_AAT;
    float* cc   = sm + SM_CC;
    float* xs   = sm + SM_XS;
    float* qs   = sm + SM_QS;

    const int tid = threadIdx.x;
    const int b = blockIdx.y;
    const int s = blockIdx.x;

    // ---- stage transposed params in shared ----
    for (int i = tid; i < K_ * D_; i += 256) {
        int k = i >> 6, d = i & 63;
        float v = var[i];
        float iv = 1.0f / v;
        ivhT[d * K_ + k] = -0.5f * iv;
        aaT[d * K_ + k]  = mu[i] * iv;
    }
    if (tid < K_) {
        float acc = 0.0f;
        for (int d = 0; d < D_; ++d) {
            float v = var[tid * D_ + d];
            float m = mu[tid * D_ + d];
            acc += logf(v) + m * m / v;
        }
        cc[tid] = logf(pi[tid]) - 0.5f * ((float)D_ * 1.83787706640934548356f + acc);
    }
    // first tile's __syncthreads publishes params

    // phase-1 thread map: pg (point group of 4), kg (k group of 8)
    const int pg = tid >> 3;
    const int kg = tid & 7;
    // phase-2 thread map: tk (k group of 4), td (d group of 4)
    const int tk = tid >> 4;
    const int td = tid & 15;

    u64 accX[4][2]  = {};   // Q_x  : 4 k-rows x 2 d-pairs
    u64 accX2[4][2] = {};   // Q_x2
    u64 qacc[4]     = {};   // per-thread Q column sums (4 k-pairs)

    const int n_base = s * (N_ / SPLIT_);

    for (int tile = 0; tile < TILES_; ++tile) {
        const int n0 = n_base + tile * T_;
        // ---- coalesced load of x tile ----
        const float4* xg = (const float4*)(x + ((size_t)b * N_ + n0) * (size_t)D_);
        #pragma unroll
        for (int ii = 0; ii < 8; ++ii) {
            int i = tid + ii * 256;
            float4 v = xg[i];
            int row = i >> 4, c4 = i & 15;
            *(float4*)(xs + row * XST_ + c4 * 4) = v;
        }
        __syncthreads();

        // ---- phase 1: logits via register-blocked packed GEMM ----
        u64 lp[4][4];
        {
            const u64* cc2 = (const u64*)(cc + kg * 8);
            u64 c0 = cc2[0], c1 = cc2[1], c2 = cc2[2], c3 = cc2[3];
            #pragma unroll
            for (int p = 0; p < 4; ++p) { lp[p][0]=c0; lp[p][1]=c1; lp[p][2]=c2; lp[p][3]=c3; }
        }
        #pragma unroll 4
        for (int d0 = 0; d0 < D_; d0 += 4) {
            float xvv[4][4];
            #pragma unroll
            for (int p = 0; p < 4; ++p) {
                float4 t = *(const float4*)(xs + (pg * 4 + p) * XST_ + d0);
                xvv[p][0]=t.x; xvv[p][1]=t.y; xvv[p][2]=t.z; xvv[p][3]=t.w;
            }
            #pragma unroll
            for (int dd = 0; dd < 4; ++dd) {
                const int d = d0 + dd;
                ulonglong2 ih = *(const ulonglong2*)(ivhT + d * K_ + kg * 8);
                ulonglong2 ih2 = *(const ulonglong2*)(ivhT + d * K_ + kg * 8 + 4);
                ulonglong2 av = *(const ulonglong2*)(aaT  + d * K_ + kg * 8);
                ulonglong2 av2 = *(const ulonglong2*)(aaT  + d * K_ + kg * 8 + 4);
                #pragma unroll
                for (int p = 0; p < 4; ++p) {
                    float xd = xvv[p][dd];
                    u64 xp  = pk2(xd, xd);
                    u64 x2p = mul2(xp, xp);
                    lp[p][0] = fma2(x2p, ih.x,  lp[p][0]);
                    lp[p][1] = fma2(x2p, ih.y,  lp[p][1]);
                    lp[p][2] = fma2(x2p, ih2.x, lp[p][2]);
                    lp[p][3] = fma2(x2p, ih2.y, lp[p][3]);
                    lp[p][0] = fma2(xp,  av.x,  lp[p][0]);
                    lp[p][1] = fma2(xp,  av.y,  lp[p][1]);
                    lp[p][2] = fma2(xp,  av2.x, lp[p][2]);
                    lp[p][3] = fma2(xp,  av2.y, lp[p][3]);
                }
            }
        }

        // ---- softmax over K (8 local k x 8 lanes) ----
        #pragma unroll
        for (int p = 0; p < 4; ++p) {
            float q[8];
            up2(q[0], q[1], lp[p][0]); up2(q[2], q[3], lp[p][1]);
            up2(q[4], q[5], lp[p][2]); up2(q[6], q[7], lp[p][3]);
            float mx = q[0];
            #pragma unroll
            for (int j = 1; j < 8; ++j) mx = fmaxf(mx, q[j]);
            mx = fmaxf(mx, __shfl_xor_sync(0xffffffffu, mx, 1));
            mx = fmaxf(mx, __shfl_xor_sync(0xffffffffu, mx, 2));
            mx = fmaxf(mx, __shfl_xor_sync(0xffffffffu, mx, 4));
            float sum = 0.0f;
            #pragma unroll
            for (int j = 0; j < 8; ++j) { q[j] = __expf(q[j] - mx); sum += q[j]; }
            sum += __shfl_xor_sync(0xffffffffu, sum, 1);
            sum += __shfl_xor_sync(0xffffffffu, sum, 2);
            sum += __shfl_xor_sync(0xffffffffu, sum, 4);
            float inv = __fdividef(1.0f, sum);
            u64 qp0 = pk2(q[0] * inv, q[1] * inv);
            u64 qp1 = pk2(q[2] * inv, q[3] * inv);
            u64 qp2 = pk2(q[4] * inv, q[5] * inv);
            u64 qp3 = pk2(q[6] * inv, q[7] * inv);
            qacc[0] = add2(qacc[0], qp0); qacc[1] = add2(qacc[1], qp1);
            qacc[2] = add2(qacc[2], qp2); qacc[3] = add2(qacc[3], qp3);
            ulonglong2* qdst = (ulonglong2*)(qs + (pg * 4 + p) * XST_ + kg * 8);
            qdst[0] = make_ulonglong2(qp0, qp1);
            qdst[1] = make_ulonglong2(qp2, qp3);
        }
        __syncthreads();

        // ---- phase 2: rank-T packed update of Q_x / Q_x2 ----
        #pragma unroll 4
        for (int n = 0; n < T_; ++n) {
            ulonglong2 qv = *(const ulonglong2*)(qs + n * XST_ + tk * 4);
            ulonglong2 xv = *(const ulonglong2*)(xs + n * XST_ + td * 4);
            u64 xp0 = xv.x, xp1 = xv.y;
            u64 x2p0 = mul2(xp0, xp0);
            u64 x2p1 = mul2(xp1, xp1);
            float q0, q1, q2, q3;
            up2(q0, q1, qv.x); up2(q2, q3, qv.y);
            u64 qq0 = pk2(q0, q0), qq1 = pk2(q1, q1);
            u64 qq2 = pk2(q2, q2), qq3 = pk2(q3, q3);
            accX[0][0] = fma2(qq0, xp0, accX[0][0]); accX[0][1] = fma2(qq0, xp1, accX[0][1]);
            accX[1][0] = fma2(qq1, xp0, accX[1][0]); accX[1][1] = fma2(qq1, xp1, accX[1][1]);
            accX[2][0] = fma2(qq2, xp0, accX[2][0]); accX[2][1] = fma2(qq2, xp1, accX[2][1]);
            accX[3][0] = fma2(qq3, xp0, accX[3][0]); accX[3][1] = fma2(qq3, xp1, accX[3][1]);
            accX2[0][0] = fma2(qq0, x2p0, accX2[0][0]); accX2[0][1] = fma2(qq0, x2p1, accX2[0][1]);
            accX2[1][0] = fma2(qq1, x2p0, accX2[1][0]); accX2[1][1] = fma2(qq1, x2p1, accX2[1][1]);
            accX2[2][0] = fma2(qq2, x2p0, accX2[2][0]); accX2[2][1] = fma2(qq2, x2p1, accX2[2][1]);
            accX2[3][0] = fma2(qq3, x2p0, accX2[3][0]); accX2[3][1] = fma2(qq3, x2p1, accX2[3][1]);
        }
        __syncthreads();
    }

    // ---- reduce qacc across pg groups (reuse xs as scratch) ----
    float* part = xs;   // [32][64]
    #pragma unroll
    for (int j = 0; j < 4; ++j)
        *(u64*)(part + pg * K_ + kg * 8 + 2 * j) = qacc[j];
    __syncthreads();

    float* slot = g_part + ((size_t)b * SPLIT_ + s) * SLOT_;
    if (tid < K_) {
        float qsum = 0.0f;
        #pragma unroll 8
        for (int r = 0; r < 32; ++r) qsum += part[r * K_ + tid];
        slot[tid] = qsum;
    }
    float* qxs  = slot + K_;
    float* qx2s = slot + K_ + K_ * D_;
    #pragma unroll
    for (int i = 0; i < 4; ++i) {
        int k = tk * 4 + i;
        *(ulonglong2*)(qxs  + k * D_ + td * 4) = make_ulonglong2(accX[i][0],  accX[i][1]);
        *(ulonglong2*)(qx2s + k * D_ + td * 4) = make_ulonglong2(accX2[i][0], accX2[i][1]);
    }
}

__global__ __launch_bounds__(256) void fv_final(
    const float* __restrict__ pi, const float* __restrict__ mu,
    const float* __restrict__ var, float* __restrict__ out)
{
    const int b = blockIdx.x;
    const int seg = blockIdx.y;      // 0..7, each handles 512 of K*D
    const int tid = threadIdx.x;
    __shared__ float qsum_s[K_];
    const float* base = g_part + (size_t)b * SPLIT_ * SLOT_;
    const float inv_n = 1.0f / (float)N_;

    if (tid < K_) {
        float ssum = 0.0f;
        #pragma unroll
        for (int t = 0; t < SPLIT_; ++t) ssum += base[(size_t)t * SLOT_ + tid];
        ssum *= inv_n;
        qsum_s[tid] = ssum;
        if (seg == 0) out[(size_t)b * SLOT_ + tid] = ssum - pi[tid];   // d_pi
    }
    __syncthreads();

    #pragma unroll
    for (int ii = 0; ii < 2; ++ii) {
        int idx = seg * 512 + ii * 256 + tid;
        float qx = 0.0f, qx2 = 0.0f;
        #pragma unroll
        for (int t = 0; t < SPLIT_; ++t) {
            const float* sl = base + (size_t)t * SLOT_;
            qx  += sl[K_ + idx];
            qx2 += sl[K_ + K_ * D_ + idx];
        }
        qx *= inv_n; qx2 *= inv_n;
        int k = idx >> 6;
        float m = mu[idx];
        float v = var[idx];
        float qsv = qsum_s[k];
        out[(size_t)b * SLOT_ + K_ + idx] = qx - qsv * m;                     // d_mu
        out[(size_t)b * SLOT_ + K_ + K_ * D_ + idx] =
            -qx2 - qsv * m * m + qsv * v + 2.0f * qx * m;                     // d_sigma
    }
}

extern "C" void kernel_launch(void* const* d_in, const int* in_sizes, int n_in,
                              void* d_out, int out_size)
{
    const float* x   = (const float*)d_in[0];
    const float* pi  = (const float*)d_in[1];
    const float* mu  = (const float*)d_in[2];
    const float* var = (const float*)d_in[3];
    float* out = (float*)d_out;

    size_t smem = (size_t)SM_FLOATS * sizeof(float);  // 102,656 bytes -> occ 2
    cudaFuncSetAttribute(fv_main, cudaFuncAttributeMaxDynamicSharedMemorySize, (int)smem);

    dim3 grid(SPLIT_, B_);
    fv_main<<<grid, 256, smem>>>(x, pi, mu, var);
    dim3 g2(B_, 8);
    fv_final<<<g2, 256>>>(pi, mu, var, out);
}